// round 12
// baseline (speedup 1.0000x reference)
#include <cuda_runtime.h>
#include <cuda_fp16.h>
#include <math.h>
#include <stdint.h>

#define BATCH   2
#define SEQ     2048
#define DMODEL  1024
#define NHEADS  16
#define HDIM    64
#define MTOT    (BATCH*SEQ)           // 4096
#define LOG2_THETA 13.28771238f       // log2(10000)
#define C_SCALE 0.18033688f           // log2(e)/8

// ---- GEMM tiling: A fp16, W fp16; BK=32, 4-stage ring, 1 sync/chunk ----
#define BM 128
#define BN 128
#define BKE 32
#define ROWB 80                        // 32 elems*2B + 16B pad
#define TILE_B (128*ROWB)              // 10240
#define STAGE2 (2*TILE_B)              // 20480  (A + W)
#define NSTAGE 4
#define SMEM_G (NSTAGE*STAGE2)         // 81920 -> 2 CTAs/SM

// ---- attention tiling (Kh,Kl,Vh), 3-stage ring ----
#define ATILE_B (64*144)               // 9216
#define ASTAGE  (3*ATILE_B)            // 27648
#define ANST    3
#define ASMEM   (ANST*ASTAGE)          // 82944

// ---- scratch ----
__device__ half g_x16[MTOT*DMODEL];
__device__ half g_w16[4][DMODEL*DMODEL];
__device__ half g_Qh[BATCH*NHEADS*SEQ*HDIM], g_Ql[BATCH*NHEADS*SEQ*HDIM];
__device__ half g_Kh[BATCH*NHEADS*SEQ*HDIM], g_Kl[BATCH*NHEADS*SEQ*HDIM];
__device__ half g_Vh[BATCH*NHEADS*SEQ*HDIM];
__device__ half g_a16[MTOT*DMODEL];
__device__ float2 g_rope[SEQ*32];

// ---------------------------------------------------------------------------
__device__ __forceinline__ uint32_t smem_u32(const void* p) {
    uint32_t a;
    asm("{ .reg .u64 t; cvta.to.shared.u64 t, %1; cvt.u32.u64 %0, t; }" : "=r"(a) : "l"(p));
    return a;
}
#define CP16(s, g)  asm volatile("cp.async.cg.shared.global [%0], [%1], 16;" :: "r"(s), "l"(g))
#define CPCOMMIT()  asm volatile("cp.async.commit_group;" ::: "memory")
#define CPWAIT0()   asm volatile("cp.async.wait_group 0;" ::: "memory")
#define CPWAIT1()   asm volatile("cp.async.wait_group 1;" ::: "memory")
#define CPWAIT2()   asm volatile("cp.async.wait_group 2;" ::: "memory")

#define LDMX4(r, a) asm volatile("ldmatrix.sync.aligned.m8n8.x4.shared.b16 {%0,%1,%2,%3}, [%4];" \
    : "=r"((r)[0]), "=r"((r)[1]), "=r"((r)[2]), "=r"((r)[3]) : "r"(a))
#define LDMX2(r, a) asm volatile("ldmatrix.sync.aligned.m8n8.x2.shared.b16 {%0,%1}, [%2];" \
    : "=r"((r)[0]), "=r"((r)[1]) : "r"(a))
#define LDMX2T(r, a) asm volatile("ldmatrix.sync.aligned.m8n8.x2.trans.shared.b16 {%0,%1}, [%2];" \
    : "=r"((r)[0]), "=r"((r)[1]) : "r"(a))

#define MMA16816(c, a, b) asm volatile( \
    "mma.sync.aligned.m16n8k16.row.col.f32.f16.f16.f32 " \
    "{%0,%1,%2,%3},{%4,%5,%6,%7},{%8,%9},{%0,%1,%2,%3};" \
    : "+f"((c)[0]), "+f"((c)[1]), "+f"((c)[2]), "+f"((c)[3]) \
    : "r"((a)[0]), "r"((a)[1]), "r"((a)[2]), "r"((a)[3]), "r"((b)[0]), "r"((b)[1]))

__device__ __forceinline__ float ex2(float x) {
    float r; asm("ex2.approx.ftz.f32 %0, %1;" : "=f"(r) : "f"(x)); return r;
}
__device__ __forceinline__ void split2h(float v0, float v1, half* ph, half* pl) {
    half h0 = __float2half_rn(v0), h1 = __float2half_rn(v1);
    half l0 = __float2half_rn(v0 - __half2float(h0));
    half l1 = __float2half_rn(v1 - __half2float(h1));
    half2 hv = {h0, h1}, lv = {l0, l1};
    *(half2*)ph = hv;
    *(half2*)pl = lv;
}

// ---------------------------------------------------------------------------
// conversions
// ---------------------------------------------------------------------------
__global__ __launch_bounds__(256)
void conv_f16(const float* __restrict__ in, half* __restrict__ out, int n4)
{
    int i = blockIdx.x * 256 + threadIdx.x;
    if (i >= n4) return;
    float4 v = ((const float4*)in)[i];
    half2 a = __floats2half2_rn(v.x, v.y);
    half2 b = __floats2half2_rn(v.z, v.w);
    uint2 u;
    u.x = *(uint32_t*)&a; u.y = *(uint32_t*)&b;
    ((uint2*)out)[i] = u;
}

__global__ __launch_bounds__(256)
void conv_w(const float* __restrict__ w0, const float* __restrict__ w1,
            const float* __restrict__ w2, const float* __restrict__ w3,
            half* __restrict__ out, int n4)
{
    int z = blockIdx.z;
    const float* w = (z == 0) ? w0 : (z == 1) ? w1 : (z == 2) ? w2 : w3;
    int i = blockIdx.x * 256 + threadIdx.x;
    if (i >= n4) return;
    float4 v = ((const float4*)w)[i];
    half2 a = __floats2half2_rn(v.x, v.y);
    half2 b = __floats2half2_rn(v.z, v.w);
    uint2 u;
    u.x = *(uint32_t*)&a; u.y = *(uint32_t*)&b;
    ((uint2*)out)[(size_t)z * (DMODEL * DMODEL / 4) + i] = u;
}

__global__ __launch_bounds__(256)
void rope_tab(const int* __restrict__ posarr, float2* __restrict__ tab)
{
    int i = blockIdx.x * 256 + threadIdx.x;
    int s = i >> 5, f = i & 31;
    float pos = (float)posarr[s];
    float fr = exp2f(-LOG2_THETA * (float)f * (1.0f / 32.0f));
    float sn, cs;
    sincosf(pos * fr, &sn, &cs);
    tab[i] = make_float2(cs, sn);
}

// ---------------------------------------------------------------------------
// plain fp16 HMMA GEMM: C = A @ W^T;  BK=32, 4-stage ring, one sync per chunk.
// QKV=1: fused Q/K/V via blockIdx.z; QKV=0: O projection (fp32 out)
// ---------------------------------------------------------------------------
template<int QKV>
__global__ __launch_bounds__(256, 2)
void gemm2(const half* __restrict__ A, const half* __restrict__ W0,
           float* __restrict__ outF,
           half* __restrict__ qh, half* __restrict__ ql,
           half* __restrict__ kh, half* __restrict__ kl,
           half* __restrict__ vh,
           const float2* __restrict__ rope)
{
    extern __shared__ char smem[];
    const uint32_t sb = smem_u32(smem);
    const int tid  = threadIdx.x;
    const int warp = tid >> 5;
    const int lane = tid & 31;
    const int m0 = blockIdx.y * BM;
    const int n0 = blockIdx.x * BN;
    const int z  = QKV ? blockIdx.z : 0;
    const int wm0 = (warp >> 2) * 64;
    const int wn0 = (warp & 3) * 32;

    float acc[4][4][4];
    #pragma unroll
    for (int i = 0; i < 4; i++)
        #pragma unroll
        for (int j = 0; j < 4; j++)
            #pragma unroll
            for (int k = 0; k < 4; k++) acc[i][j][k] = 0.f;

    const size_t WS = (size_t)DMODEL * DMODEL;
    const half* srcs[2] = {
        A + (size_t)m0 * DMODEL,
        W0 + (size_t)z * WS + (size_t)n0 * DMODEL
    };

    auto issue = [&](int buf, int chunk) {
        const int kof = chunk * BKE;
        #pragma unroll
        for (int t = 0; t < 4; t++) {
            int j = t * 256 + tid;
            int tile = j >> 9;
            int v = j & 511;
            int row = v >> 2, c = v & 3;
            const half* g = srcs[tile] + (size_t)row * DMODEL + kof + c * 8;
            uint32_t s = sb + buf * STAGE2 + tile * TILE_B + row * ROWB + c * 16;
            CP16(s, g);
        }
        CPCOMMIT();
    };

    issue(0, 0);
    issue(1, 1);
    issue(2, 2);

    const int NCH = DMODEL / BKE;       // 32
    for (int i = 0; i < NCH; i++) {
        // groups in flight beyond i: min(2, NCH-1-i)
        if (i <= NCH - 4)      CPWAIT2();
        else if (i == NCH - 3) CPWAIT2();
        else if (i == NCH - 2) CPWAIT1();
        else                   CPWAIT0();
        __syncthreads();
        if (i + 3 < NCH) issue((i + 3) % NSTAGE, i + 3);

        const uint32_t base = sb + (i % NSTAGE) * STAGE2;
        #pragma unroll
        for (int ks = 0; ks < 2; ks++) {
            uint32_t af[4][4], bf[4][2];
            const int arow = wm0 + (lane & 15);
            const int acolB = (ks * 16 + (lane >> 4) * 8) * 2;
            #pragma unroll
            for (int mi = 0; mi < 4; mi++)
                LDMX4(af[mi], base + (arow + mi * 16) * ROWB + acolB);
            const int brow = wn0 + (lane & 7);
            const int bcolB = (ks * 16 + ((lane >> 3) & 1) * 8) * 2;
            #pragma unroll
            for (int ni = 0; ni < 4; ni++)
                LDMX2(bf[ni], base + 1 * TILE_B + (brow + ni * 8) * ROWB + bcolB);
            #pragma unroll
            for (int mi = 0; mi < 4; mi++)
                #pragma unroll
                for (int ni = 0; ni < 4; ni++)
                    MMA16816(acc[mi][ni], af[mi], bf[ni]);
        }
    }

    __syncthreads();
    const int r = lane >> 2;
    const int cc = (lane & 3) * 2;
    #pragma unroll
    for (int mi = 0; mi < 4; mi++) {
        #pragma unroll
        for (int ni = 0; ni < 4; ni++) {
            int mg = m0 + wm0 + mi * 16 + r;
            int ng = n0 + wn0 + ni * 8 + cc;
            #pragma unroll
            for (int half_i = 0; half_i < 2; half_i++) {
                int m = mg + half_i * 8;
                float e = acc[mi][ni][half_i * 2 + 0];
                float o = acc[mi][ni][half_i * 2 + 1];
                if (QKV == 0) {
                    float2 v = {e, o};
                    *(float2*)&outF[(size_t)m * DMODEL + ng] = v;
                } else {
                    int h = ng >> 6, nh = ng & 63;
                    int b = m >> 11, s = m & (SEQ - 1);
                    size_t off = (((size_t)(b * NHEADS + h) * SEQ + s) << 6) + nh;
                    if (z < 2) {
                        float2 csn = rope[s * 32 + (nh >> 1)];
                        float re = e * csn.x - o * csn.y;
                        float ro = e * csn.y + o * csn.x;
                        if (z == 0) split2h(re, ro, qh + off, ql + off);
                        else        split2h(re, ro, kh + off, kl + off);
                    } else {
                        half2 v = __floats2half2_rn(e, o);
                        *(half2*)(vh + off) = v;
                    }
                }
            }
        }
    }
}

// ---------------------------------------------------------------------------
// HMMA flash attention, causal. QK 3-product (split q/k), PV 1-product.
// 3-stage ring, one sync per kv-block.
// ---------------------------------------------------------------------------
__global__ __launch_bounds__(256)
void attn_mma(const half* __restrict__ Qh, const half* __restrict__ Ql,
              const half* __restrict__ Kh, const half* __restrict__ Kl,
              const half* __restrict__ Vh,
              half* __restrict__ outA)
{
    extern __shared__ char smem[];
    const uint32_t sb = smem_u32(smem);
    const int tid = threadIdx.x, warp = tid >> 5, lane = tid & 31;
    const int g = lane >> 2, t = lane & 3;
    const int qb = (int)gridDim.x - 1 - (int)blockIdx.x;
    const int bh = blockIdx.y;
    const size_t bhoff = (size_t)bh * SEQ * HDIM;
    const int qrow0 = qb * 128 + warp * 16;

    uint32_t qa_h[4][4], qa_l[4][4];
    {
        const half* Qbh = Qh + bhoff + (size_t)qrow0 * 64;
        const half* Qbl = Ql + bhoff + (size_t)qrow0 * 64;
        #pragma unroll
        for (int u = 0; u < 4; u++) {
            int c0 = u * 16 + 2 * t;
            qa_h[u][0] = *(const uint32_t*)(Qbh + (g    ) * 64 + c0);
            qa_h[u][1] = *(const uint32_t*)(Qbh + (g + 8) * 64 + c0);
            qa_h[u][2] = *(const uint32_t*)(Qbh + (g    ) * 64 + c0 + 8);
            qa_h[u][3] = *(const uint32_t*)(Qbh + (g + 8) * 64 + c0 + 8);
            qa_l[u][0] = *(const uint32_t*)(Qbl + (g    ) * 64 + c0);
            qa_l[u][1] = *(const uint32_t*)(Qbl + (g + 8) * 64 + c0);
            qa_l[u][2] = *(const uint32_t*)(Qbl + (g    ) * 64 + c0 + 8);
            qa_l[u][3] = *(const uint32_t*)(Qbl + (g + 8) * 64 + c0 + 8);
        }
    }

    float accO[8][4];
    #pragma unroll
    for (int i = 0; i < 8; i++)
        #pragma unroll
        for (int j = 0; j < 4; j++) accO[i][j] = 0.f;
    float m0 = -1e38f, m1 = -1e38f, l0 = 0.f, l1 = 0.f;

    const int nkb = 2 * qb + 2;
    const half* srcs[3] = {Kh + bhoff, Kl + bhoff, Vh + bhoff};

    auto issue = [&](int buf, int kb) {
        #pragma unroll
        for (int it = 0; it < 6; it++) {
            int j = it * 256 + tid;
            int tile = j >> 9, v = j & 511, row = v >> 3, c = v & 7;
            const half* gp = srcs[tile] + (((size_t)(kb * 64 + row)) << 6) + c * 8;
            uint32_t sa = sb + buf * ASTAGE + tile * ATILE_B + row * 144 + c * 16;
            CP16(sa, gp);
        }
        CPCOMMIT();
    };

    issue(0, 0);
    if (nkb > 1) issue(1, 1);

    for (int kb = 0; kb < nkb; kb++) {
        if (kb < nkb - 1) CPWAIT1(); else CPWAIT0();
        __syncthreads();
        if (kb + 2 < nkb) issue((kb + 2) % ANST, kb + 2);

        const uint32_t base = sb + (kb % ANST) * ASTAGE;

        float S[8][4];
        #pragma unroll
        for (int i = 0; i < 8; i++)
            #pragma unroll
            for (int j = 0; j < 4; j++) S[i][j] = 0.f;

        #pragma unroll
        for (int nt = 0; nt < 8; nt++) {
            #pragma unroll
            for (int u = 0; u < 4; u++) {
                uint32_t off = (nt * 8 + (lane & 7)) * 144 + (u * 16 + ((lane >> 3) & 1) * 8) * 2;
                uint32_t kh2[2], kl2[2];
                LDMX2(kh2, base + 0 * ATILE_B + off);
                LDMX2(kl2, base + 1 * ATILE_B + off);
                MMA16816(S[nt], qa_h[u], kh2);
                MMA16816(S[nt], qa_h[u], kl2);
                MMA16816(S[nt], qa_l[u], kh2);
            }
        }

        if (kb * 64 + 63 > qrow0) {
            #pragma unroll
            for (int nt = 0; nt < 8; nt++) {
                int key = kb * 64 + nt * 8 + 2 * t;
                int r0 = qrow0 + g, r1 = r0 + 8;
                if (key     > r0) S[nt][0] = -1e30f;
                if (key + 1 > r0) S[nt][1] = -1e30f;
                if (key     > r1) S[nt][2] = -1e30f;
                if (key + 1 > r1) S[nt][3] = -1e30f;
            }
        }

        float mx0 = -1e38f, mx1 = -1e38f;
        #pragma unroll
        for (int nt = 0; nt < 8; nt++) {
            mx0 = fmaxf(mx0, fmaxf(S[nt][0], S[nt][1]));
            mx1 = fmaxf(mx1, fmaxf(S[nt][2], S[nt][3]));
        }
        mx0 = fmaxf(mx0, __shfl_xor_sync(0xffffffffu, mx0, 1));
        mx0 = fmaxf(mx0, __shfl_xor_sync(0xffffffffu, mx0, 2));
        mx1 = fmaxf(mx1, __shfl_xor_sync(0xffffffffu, mx1, 1));
        mx1 = fmaxf(mx1, __shfl_xor_sync(0xffffffffu, mx1, 2));
        float mN0 = fmaxf(m0, mx0), mN1 = fmaxf(m1, mx1);
        float sc0 = ex2((m0 - mN0) * C_SCALE);
        float sc1 = ex2((m1 - mN1) * C_SCALE);
        m0 = mN0; m1 = mN1;
        l0 *= sc0; l1 *= sc1;
        #pragma unroll
        for (int nt = 0; nt < 8; nt++) {
            accO[nt][0] *= sc0; accO[nt][1] *= sc0;
            accO[nt][2] *= sc1; accO[nt][3] *= sc1;
        }

        uint32_t Ph[8][2];
        #pragma unroll
        for (int nt = 0; nt < 8; nt++) {
            float p0 = ex2((S[nt][0] - m0) * C_SCALE);
            float p1 = ex2((S[nt][1] - m0) * C_SCALE);
            float p2 = ex2((S[nt][2] - m1) * C_SCALE);
            float p3 = ex2((S[nt][3] - m1) * C_SCALE);
            l0 += p0 + p1;
            l1 += p2 + p3;
            half2 h01 = __floats2half2_rn(p0, p1);
            half2 h23 = __floats2half2_rn(p2, p3);
            Ph[nt][0] = *(uint32_t*)&h01; Ph[nt][1] = *(uint32_t*)&h23;
        }

        #pragma unroll
        for (int u = 0; u < 4; u++) {
            uint32_t aph[4] = {Ph[2*u][0], Ph[2*u][1], Ph[2*u+1][0], Ph[2*u+1][1]};
            #pragma unroll
            for (int nt = 0; nt < 8; nt++) {
                uint32_t voff = (u * 16 + (lane & 15)) * 144 + nt * 8 * 2;
                uint32_t vh2[2];
                LDMX2T(vh2, base + 2 * ATILE_B + voff);
                MMA16816(accO[nt], aph, vh2);
            }
        }
    }

    l0 += __shfl_xor_sync(0xffffffffu, l0, 1);
    l0 += __shfl_xor_sync(0xffffffffu, l0, 2);
    l1 += __shfl_xor_sync(0xffffffffu, l1, 1);
    l1 += __shfl_xor_sync(0xffffffffu, l1, 2);
    float inv0 = 1.0f / l0, inv1 = 1.0f / l1;

    const int b = bh >> 4, h = bh & 15;
    const int s0 = qrow0 + g, s1 = s0 + 8;
    #pragma unroll
    for (int nt = 0; nt < 8; nt++) {
        int col = h * 64 + nt * 8 + 2 * t;
        size_t i0 = ((size_t)(b * SEQ + s0)) * DMODEL + col;
        size_t i1 = ((size_t)(b * SEQ + s1)) * DMODEL + col;
        half2 o0 = __floats2half2_rn(accO[nt][0] * inv0, accO[nt][1] * inv0);
        half2 o1 = __floats2half2_rn(accO[nt][2] * inv1, accO[nt][3] * inv1);
        *(half2*)(outA + i0) = o0;
        *(half2*)(outA + i1) = o1;
    }
}

// ---------------------------------------------------------------------------
extern "C" void kernel_launch(void* const* d_in, const int* in_sizes, int n_in,
                              void* d_out, int out_size)
{
    const float* x   = (const float*)d_in[0];
    const float* Wq  = (const float*)d_in[1];
    const float* Wk  = (const float*)d_in[2];
    const float* Wv  = (const float*)d_in[3];
    const float* Wo  = (const float*)d_in[4];
    const int*   pos = (const int*)d_in[6];
    float* out       = (float*)d_out;

    half *x16, *w16, *qh, *ql, *kh, *kl, *vh, *a16;
    float2* rtab;
    cudaGetSymbolAddress((void**)&x16, g_x16);
    cudaGetSymbolAddress((void**)&w16, g_w16);
    cudaGetSymbolAddress((void**)&qh, g_Qh);  cudaGetSymbolAddress((void**)&ql, g_Ql);
    cudaGetSymbolAddress((void**)&kh, g_Kh);  cudaGetSymbolAddress((void**)&kl, g_Kl);
    cudaGetSymbolAddress((void**)&vh, g_Vh);
    cudaGetSymbolAddress((void**)&a16, g_a16);
    cudaGetSymbolAddress((void**)&rtab, g_rope);

    cudaFuncSetAttribute(gemm2<0>, cudaFuncAttributeMaxDynamicSharedMemorySize, SMEM_G);
    cudaFuncSetAttribute(gemm2<1>, cudaFuncAttributeMaxDynamicSharedMemorySize, SMEM_G);
    cudaFuncSetAttribute(attn_mma, cudaFuncAttributeMaxDynamicSharedMemorySize, ASMEM);

    const int NX4 = MTOT * DMODEL / 4;
    const int NW4 = DMODEL * DMODEL / 4;
    const size_t WS = (size_t)DMODEL * DMODEL;

    conv_f16<<<NX4 / 256, 256>>>(x, x16, NX4);
    {
        dim3 gw(NW4 / 256, 1, 4);
        conv_w<<<gw, 256>>>(Wq, Wk, Wv, Wo, w16, NW4);
    }
    rope_tab<<<(SEQ * 32) / 256, 256>>>(pos, rtab);

    dim3 gq(DMODEL / BN, MTOT / BM, 3);      // (8, 32, 3) = 768 CTAs
    gemm2<1><<<gq, 256, SMEM_G>>>(x16, w16, nullptr, qh, ql, kh, kl, vh, rtab);

    dim3 ga(SEQ / 128, BATCH * NHEADS);      // (16, 32) = 512 CTAs
    attn_mma<<<ga, 256, ASMEM>>>(qh, ql, kh, kl, vh, a16);

    dim3 go(DMODEL / BN, MTOT / BM, 1);      // (8, 32)
    gemm2<0><<<go, 256, SMEM_G>>>(a16, w16 + 3 * WS, out,
                                  nullptr, nullptr, nullptr, nullptr, nullptr, rtab);
}

// round 15
// speedup vs baseline: 1.0935x; 1.0935x over previous
#include <cuda_runtime.h>
#include <cuda_fp16.h>
#include <math.h>
#include <stdint.h>

#define BATCH   2
#define SEQ     2048
#define DMODEL  1024
#define NHEADS  16
#define HDIM    64
#define MTOT    (BATCH*SEQ)           // 4096
#define LOG2_THETA 13.28771238f       // log2(10000)
#define C_SCALE 0.18033688f           // log2(e)/8

// ---- GEMM tiling: A fp16, W fp16; BK=64, 3-stage ring, pipelined frags ----
#define BM 128
#define BN 128
#define BKE 64
#define ROWB 144                       // 64*2 + 16 pad; 144/16=9 -> conflict-free
#define TILE_B (128*ROWB)              // 18432
#define STAGE2 (2*TILE_B)              // 36864  (A + W)
#define NSTAGE 3
#define SMEM_G (NSTAGE*STAGE2)         // 110592 -> 2 CTAs/SM

// ---- attention tiling (Kh,Kl,Vh), 2-stage double buffer (R10 winner) ----
#define ATILE_B (64*144)               // 9216
#define ASTAGE  (3*ATILE_B)            // 27648
#define ASMEM   (2*ASTAGE)             // 55296

// ---- scratch ----
__device__ half g_x16[MTOT*DMODEL];
__device__ half g_w16[4][DMODEL*DMODEL];
__device__ half g_Qh[BATCH*NHEADS*SEQ*HDIM], g_Ql[BATCH*NHEADS*SEQ*HDIM];
__device__ half g_Kh[BATCH*NHEADS*SEQ*HDIM], g_Kl[BATCH*NHEADS*SEQ*HDIM];
__device__ half g_Vh[BATCH*NHEADS*SEQ*HDIM];
__device__ half g_a16[MTOT*DMODEL];
__device__ float2 g_rope[SEQ*32];

// ---------------------------------------------------------------------------
__device__ __forceinline__ uint32_t smem_u32(const void* p) {
    uint32_t a;
    asm("{ .reg .u64 t; cvta.to.shared.u64 t, %1; cvt.u32.u64 %0, t; }" : "=r"(a) : "l"(p));
    return a;
}
#define CP16(s, g)  asm volatile("cp.async.cg.shared.global [%0], [%1], 16;" :: "r"(s), "l"(g))
#define CPCOMMIT()  asm volatile("cp.async.commit_group;" ::: "memory")
#define CPWAIT0()   asm volatile("cp.async.wait_group 0;" ::: "memory")
#define CPWAIT1()   asm volatile("cp.async.wait_group 1;" ::: "memory")

#define LDMX4(r, a) asm volatile("ldmatrix.sync.aligned.m8n8.x4.shared.b16 {%0,%1,%2,%3}, [%4];" \
    : "=r"((r)[0]), "=r"((r)[1]), "=r"((r)[2]), "=r"((r)[3]) : "r"(a))
#define LDMX2(r, a) asm volatile("ldmatrix.sync.aligned.m8n8.x2.shared.b16 {%0,%1}, [%2];" \
    : "=r"((r)[0]), "=r"((r)[1]) : "r"(a))
#define LDMX2T(r, a) asm volatile("ldmatrix.sync.aligned.m8n8.x2.trans.shared.b16 {%0,%1}, [%2];" \
    : "=r"((r)[0]), "=r"((r)[1]) : "r"(a))

#define MMA16816(c, a, b) asm volatile( \
    "mma.sync.aligned.m16n8k16.row.col.f32.f16.f16.f32 " \
    "{%0,%1,%2,%3},{%4,%5,%6,%7},{%8,%9},{%0,%1,%2,%3};" \
    : "+f"((c)[0]), "+f"((c)[1]), "+f"((c)[2]), "+f"((c)[3]) \
    : "r"((a)[0]), "r"((a)[1]), "r"((a)[2]), "r"((a)[3]), "r"((b)[0]), "r"((b)[1]))

__device__ __forceinline__ float ex2(float x) {
    float r; asm("ex2.approx.ftz.f32 %0, %1;" : "=f"(r) : "f"(x)); return r;
}
__device__ __forceinline__ void split2h(float v0, float v1, half* ph, half* pl) {
    half h0 = __float2half_rn(v0), h1 = __float2half_rn(v1);
    half l0 = __float2half_rn(v0 - __half2float(h0));
    half l1 = __float2half_rn(v1 - __half2float(h1));
    half2 hv = {h0, h1}, lv = {l0, l1};
    *(half2*)ph = hv;
    *(half2*)pl = lv;
}

// ---------------------------------------------------------------------------
// conversions
// ---------------------------------------------------------------------------
__global__ __launch_bounds__(256)
void conv_f16(const float* __restrict__ in, half* __restrict__ out, int n4)
{
    int i = blockIdx.x * 256 + threadIdx.x;
    if (i >= n4) return;
    float4 v = ((const float4*)in)[i];
    half2 a = __floats2half2_rn(v.x, v.y);
    half2 b = __floats2half2_rn(v.z, v.w);
    uint2 u;
    u.x = *(uint32_t*)&a; u.y = *(uint32_t*)&b;
    ((uint2*)out)[i] = u;
}

__global__ __launch_bounds__(256)
void conv_w(const float* __restrict__ w0, const float* __restrict__ w1,
            const float* __restrict__ w2, const float* __restrict__ w3,
            half* __restrict__ out, int n4)
{
    int z = blockIdx.z;
    const float* w = (z == 0) ? w0 : (z == 1) ? w1 : (z == 2) ? w2 : w3;
    int i = blockIdx.x * 256 + threadIdx.x;
    if (i >= n4) return;
    float4 v = ((const float4*)w)[i];
    half2 a = __floats2half2_rn(v.x, v.y);
    half2 b = __floats2half2_rn(v.z, v.w);
    uint2 u;
    u.x = *(uint32_t*)&a; u.y = *(uint32_t*)&b;
    ((uint2*)out)[(size_t)z * (DMODEL * DMODEL / 4) + i] = u;
}

__global__ __launch_bounds__(256)
void rope_tab(const int* __restrict__ posarr, float2* __restrict__ tab)
{
    int i = blockIdx.x * 256 + threadIdx.x;
    int s = i >> 5, f = i & 31;
    float pos = (float)posarr[s];
    float fr = exp2f(-LOG2_THETA * (float)f * (1.0f / 32.0f));
    float sn, cs;
    sincosf(pos * fr, &sn, &cs);
    tab[i] = make_float2(cs, sn);
}

// ---------------------------------------------------------------------------
// plain fp16 HMMA GEMM: C = A @ W^T; BK=64, 3-stage ring, 1 sync/chunk,
// register-pipelined fragment loads, paired-LDMX4 B fragments.
// QKV=1: fused Q/K/V via blockIdx.z; QKV=0: O projection (fp32 out)
// ---------------------------------------------------------------------------
template<int QKV>
__global__ __launch_bounds__(256, 2)
void gemm2(const half* __restrict__ A, const half* __restrict__ W0,
           float* __restrict__ outF,
           half* __restrict__ qh, half* __restrict__ ql,
           half* __restrict__ kh, half* __restrict__ kl,
           half* __restrict__ vh,
           const float2* __restrict__ rope)
{
    extern __shared__ char smem[];
    const uint32_t sb = smem_u32(smem);
    const int tid  = threadIdx.x;
    const int warp = tid >> 5;
    const int lane = tid & 31;
    const int m0 = blockIdx.y * BM;
    const int n0 = blockIdx.x * BN;
    const int z  = QKV ? blockIdx.z : 0;
    const int wm0 = (warp >> 2) * 64;
    const int wn0 = (warp & 3) * 32;

    float acc[4][4][4];
    #pragma unroll
    for (int i = 0; i < 4; i++)
        #pragma unroll
        for (int j = 0; j < 4; j++)
            #pragma unroll
            for (int k = 0; k < 4; k++) acc[i][j][k] = 0.f;

    const size_t WS = (size_t)DMODEL * DMODEL;
    const half* srcs[2] = {
        A + (size_t)m0 * DMODEL,
        W0 + (size_t)z * WS + (size_t)n0 * DMODEL
    };

    // stage = 2 tiles x 128 rows x 64 elems = 2048 x 16B vecs, 8/thread
    auto issue = [&](int buf, int chunk) {
        const int kof = chunk * BKE;
        #pragma unroll
        for (int t = 0; t < 8; t++) {
            int j = t * 256 + tid;
            int tile = j >> 10;
            int v = j & 1023;
            int row = v >> 3, c = v & 7;
            const half* g = srcs[tile] + (size_t)row * DMODEL + kof + c * 8;
            uint32_t s = sb + buf * STAGE2 + tile * TILE_B + row * ROWB + c * 16;
            CP16(s, g);
        }
        CPCOMMIT();
    };

    issue(0, 0);
    issue(1, 1);

    const int arow  = wm0 + (lane & 15);
    const int asel  = (lane >> 4) * 8;                    // k-half select for A
    const int brow  = wn0 + (lane & 7) + ((lane >> 4) << 3);  // ni-pair rows
    const int bsel  = ((lane >> 3) & 1) * 8;              // k-half select for B

    uint32_t af[2][4][4], bf[2][2][4];

    const int NCH = DMODEL / BKE;       // 16
    for (int i = 0; i < NCH; i++) {
        if (i < NCH - 1) CPWAIT1(); else CPWAIT0();
        __syncthreads();
        if (i + 2 < NCH) issue((i + 2) % NSTAGE, i + 2);

        const uint32_t base  = sb + (i % NSTAGE) * STAGE2;
        const uint32_t baseB = base + TILE_B;

        // preload ks=0 fragments
        {
            const int ac = asel * 2;
            #pragma unroll
            for (int mi = 0; mi < 4; mi++)
                LDMX4(af[0][mi], base + (arow + mi * 16) * ROWB + ac);
            const int bc = bsel * 2;
            #pragma unroll
            for (int p = 0; p < 2; p++)
                LDMX4(bf[0][p], baseB + (brow + p * 16) * ROWB + bc);
        }
        #pragma unroll
        for (int ks = 0; ks < 4; ks++) {
            const int cur = ks & 1, nxt = cur ^ 1;
            if (ks < 3) {
                const int ac = ((ks + 1) * 16 + asel) * 2;
                #pragma unroll
                for (int mi = 0; mi < 4; mi++)
                    LDMX4(af[nxt][mi], base + (arow + mi * 16) * ROWB + ac);
                const int bc = ((ks + 1) * 16 + bsel) * 2;
                #pragma unroll
                for (int p = 0; p < 2; p++)
                    LDMX4(bf[nxt][p], baseB + (brow + p * 16) * ROWB + bc);
            }
            #pragma unroll
            for (int mi = 0; mi < 4; mi++) {
                #pragma unroll
                for (int p = 0; p < 2; p++) {
                    MMA16816(acc[mi][2*p    ], af[cur][mi], bf[cur][p]);
                    MMA16816(acc[mi][2*p + 1], af[cur][mi], bf[cur][p] + 2);
                }
            }
        }
    }

    __syncthreads();
    const int r = lane >> 2;
    const int cc = (lane & 3) * 2;
    #pragma unroll
    for (int mi = 0; mi < 4; mi++) {
        #pragma unroll
        for (int ni = 0; ni < 4; ni++) {
            int mg = m0 + wm0 + mi * 16 + r;
            int ng = n0 + wn0 + ni * 8 + cc;
            #pragma unroll
            for (int half_i = 0; half_i < 2; half_i++) {
                int m = mg + half_i * 8;
                float e = acc[mi][ni][half_i * 2 + 0];
                float o = acc[mi][ni][half_i * 2 + 1];
                if (QKV == 0) {
                    float2 v = {e, o};
                    *(float2*)&outF[(size_t)m * DMODEL + ng] = v;
                } else {
                    int h = ng >> 6, nh = ng & 63;
                    int b = m >> 11, s = m & (SEQ - 1);
                    size_t off = (((size_t)(b * NHEADS + h) * SEQ + s) << 6) + nh;
                    if (z < 2) {
                        float2 csn = rope[s * 32 + (nh >> 1)];
                        float re = e * csn.x - o * csn.y;
                        float ro = e * csn.y + o * csn.x;
                        if (z == 0) split2h(re, ro, qh + off, ql + off);
                        else        split2h(re, ro, kh + off, kl + off);
                    } else {
                        half2 v = __floats2half2_rn(e, o);
                        *(half2*)(vh + off) = v;
                    }
                }
            }
        }
    }
}

// ---------------------------------------------------------------------------
// HMMA flash attention, causal (R10 winner, verbatim). QK 3-product, PV 1.
// ---------------------------------------------------------------------------
__global__ __launch_bounds__(256)
void attn_mma(const half* __restrict__ Qh, const half* __restrict__ Ql,
              const half* __restrict__ Kh, const half* __restrict__ Kl,
              const half* __restrict__ Vh,
              half* __restrict__ outA)
{
    extern __shared__ char smem[];
    const uint32_t sb = smem_u32(smem);
    const int tid = threadIdx.x, warp = tid >> 5, lane = tid & 31;
    const int g = lane >> 2, t = lane & 3;
    const int qb = (int)gridDim.x - 1 - (int)blockIdx.x;
    const int bh = blockIdx.y;
    const size_t bhoff = (size_t)bh * SEQ * HDIM;
    const int qrow0 = qb * 128 + warp * 16;

    uint32_t qa_h[4][4], qa_l[4][4];
    {
        const half* Qbh = Qh + bhoff + (size_t)qrow0 * 64;
        const half* Qbl = Ql + bhoff + (size_t)qrow0 * 64;
        #pragma unroll
        for (int u = 0; u < 4; u++) {
            int c0 = u * 16 + 2 * t;
            qa_h[u][0] = *(const uint32_t*)(Qbh + (g    ) * 64 + c0);
            qa_h[u][1] = *(const uint32_t*)(Qbh + (g + 8) * 64 + c0);
            qa_h[u][2] = *(const uint32_t*)(Qbh + (g    ) * 64 + c0 + 8);
            qa_h[u][3] = *(const uint32_t*)(Qbh + (g + 8) * 64 + c0 + 8);
            qa_l[u][0] = *(const uint32_t*)(Qbl + (g    ) * 64 + c0);
            qa_l[u][1] = *(const uint32_t*)(Qbl + (g + 8) * 64 + c0);
            qa_l[u][2] = *(const uint32_t*)(Qbl + (g    ) * 64 + c0 + 8);
            qa_l[u][3] = *(const uint32_t*)(Qbl + (g + 8) * 64 + c0 + 8);
        }
    }

    float accO[8][4];
    #pragma unroll
    for (int i = 0; i < 8; i++)
        #pragma unroll
        for (int j = 0; j < 4; j++) accO[i][j] = 0.f;
    float m0 = -1e38f, m1 = -1e38f, l0 = 0.f, l1 = 0.f;

    const int nkb = 2 * qb + 2;
    const half* srcs[3] = {Kh + bhoff, Kl + bhoff, Vh + bhoff};

    auto issue = [&](int buf, int kb) {
        #pragma unroll
        for (int it = 0; it < 6; it++) {
            int j = it * 256 + tid;
            int tile = j >> 9, v = j & 511, row = v >> 3, c = v & 7;
            const half* gp = srcs[tile] + (((size_t)(kb * 64 + row)) << 6) + c * 8;
            uint32_t sa = sb + buf * ASTAGE + tile * ATILE_B + row * 144 + c * 16;
            CP16(sa, gp);
        }
        CPCOMMIT();
    };

    issue(0, 0);

    for (int kb = 0; kb < nkb; kb++) {
        if (kb + 1 < nkb) { issue((kb + 1) & 1, kb + 1); CPWAIT1(); }
        else              { CPWAIT0(); }
        __syncthreads();

        const uint32_t base = sb + (kb & 1) * ASTAGE;

        float S[8][4];
        #pragma unroll
        for (int i = 0; i < 8; i++)
            #pragma unroll
            for (int j = 0; j < 4; j++) S[i][j] = 0.f;

        #pragma unroll
        for (int nt = 0; nt < 8; nt++) {
            #pragma unroll
            for (int u = 0; u < 4; u++) {
                uint32_t off = (nt * 8 + (lane & 7)) * 144 + (u * 16 + ((lane >> 3) & 1) * 8) * 2;
                uint32_t kh2[2], kl2[2];
                LDMX2(kh2, base + 0 * ATILE_B + off);
                LDMX2(kl2, base + 1 * ATILE_B + off);
                MMA16816(S[nt], qa_h[u], kh2);
                MMA16816(S[nt], qa_h[u], kl2);
                MMA16816(S[nt], qa_l[u], kh2);
            }
        }

        if (kb * 64 + 63 > qrow0) {
            #pragma unroll
            for (int nt = 0; nt < 8; nt++) {
                int key = kb * 64 + nt * 8 + 2 * t;
                int r0 = qrow0 + g, r1 = r0 + 8;
                if (key     > r0) S[nt][0] = -1e30f;
                if (key + 1 > r0) S[nt][1] = -1e30f;
                if (key     > r1) S[nt][2] = -1e30f;
                if (key + 1 > r1) S[nt][3] = -1e30f;
            }
        }

        float mx0 = -1e38f, mx1 = -1e38f;
        #pragma unroll
        for (int nt = 0; nt < 8; nt++) {
            mx0 = fmaxf(mx0, fmaxf(S[nt][0], S[nt][1]));
            mx1 = fmaxf(mx1, fmaxf(S[nt][2], S[nt][3]));
        }
        mx0 = fmaxf(mx0, __shfl_xor_sync(0xffffffffu, mx0, 1));
        mx0 = fmaxf(mx0, __shfl_xor_sync(0xffffffffu, mx0, 2));
        mx1 = fmaxf(mx1, __shfl_xor_sync(0xffffffffu, mx1, 1));
        mx1 = fmaxf(mx1, __shfl_xor_sync(0xffffffffu, mx1, 2));
        float mN0 = fmaxf(m0, mx0), mN1 = fmaxf(m1, mx1);
        float sc0 = ex2((m0 - mN0) * C_SCALE);
        float sc1 = ex2((m1 - mN1) * C_SCALE);
        m0 = mN0; m1 = mN1;
        l0 *= sc0; l1 *= sc1;
        #pragma unroll
        for (int nt = 0; nt < 8; nt++) {
            accO[nt][0] *= sc0; accO[nt][1] *= sc0;
            accO[nt][2] *= sc1; accO[nt][3] *= sc1;
        }

        uint32_t Ph[8][2];
        #pragma unroll
        for (int nt = 0; nt < 8; nt++) {
            float p0 = ex2((S[nt][0] - m0) * C_SCALE);
            float p1 = ex2((S[nt][1] - m0) * C_SCALE);
            float p2 = ex2((S[nt][2] - m1) * C_SCALE);
            float p3 = ex2((S[nt][3] - m1) * C_SCALE);
            l0 += p0 + p1;
            l1 += p2 + p3;
            half2 h01 = __floats2half2_rn(p0, p1);
            half2 h23 = __floats2half2_rn(p2, p3);
            Ph[nt][0] = *(uint32_t*)&h01; Ph[nt][1] = *(uint32_t*)&h23;
        }

        #pragma unroll
        for (int u = 0; u < 4; u++) {
            uint32_t aph[4] = {Ph[2*u][0], Ph[2*u][1], Ph[2*u+1][0], Ph[2*u+1][1]};
            #pragma unroll
            for (int nt = 0; nt < 8; nt++) {
                uint32_t voff = (u * 16 + (lane & 15)) * 144 + nt * 8 * 2;
                uint32_t vh2[2];
                LDMX2T(vh2, base + 2 * ATILE_B + voff);
                MMA16816(accO[nt], aph, vh2);
            }
        }
        __syncthreads();
    }

    l0 += __shfl_xor_sync(0xffffffffu, l0, 1);
    l0 += __shfl_xor_sync(0xffffffffu, l0, 2);
    l1 += __shfl_xor_sync(0xffffffffu, l1, 1);
    l1 += __shfl_xor_sync(0xffffffffu, l1, 2);
    float inv0 = 1.0f / l0, inv1 = 1.0f / l1;

    const int b = bh >> 4, h = bh & 15;
    const int s0 = qrow0 + g, s1 = s0 + 8;
    #pragma unroll
    for (int nt = 0; nt < 8; nt++) {
        int col = h * 64 + nt * 8 + 2 * t;
        size_t i0 = ((size_t)(b * SEQ + s0)) * DMODEL + col;
        size_t i1 = ((size_t)(b * SEQ + s1)) * DMODEL + col;
        half2 o0 = __floats2half2_rn(accO[nt][0] * inv0, accO[nt][1] * inv0);
        half2 o1 = __floats2half2_rn(accO[nt][2] * inv1, accO[nt][3] * inv1);
        *(half2*)(outA + i0) = o0;
        *(half2*)(outA + i1) = o1;
    }
}

// ---------------------------------------------------------------------------
extern "C" void kernel_launch(void* const* d_in, const int* in_sizes, int n_in,
                              void* d_out, int out_size)
{
    const float* x   = (const float*)d_in[0];
    const float* Wq  = (const float*)d_in[1];
    const float* Wk  = (const float*)d_in[2];
    const float* Wv  = (const float*)d_in[3];
    const float* Wo  = (const float*)d_in[4];
    const int*   pos = (const int*)d_in[6];
    float* out       = (float*)d_out;

    half *x16, *w16, *qh, *ql, *kh, *kl, *vh, *a16;
    float2* rtab;
    cudaGetSymbolAddress((void**)&x16, g_x16);
    cudaGetSymbolAddress((void**)&w16, g_w16);
    cudaGetSymbolAddress((void**)&qh, g_Qh);  cudaGetSymbolAddress((void**)&ql, g_Ql);
    cudaGetSymbolAddress((void**)&kh, g_Kh);  cudaGetSymbolAddress((void**)&kl, g_Kl);
    cudaGetSymbolAddress((void**)&vh, g_Vh);
    cudaGetSymbolAddress((void**)&a16, g_a16);
    cudaGetSymbolAddress((void**)&rtab, g_rope);

    cudaFuncSetAttribute(gemm2<0>, cudaFuncAttributeMaxDynamicSharedMemorySize, SMEM_G);
    cudaFuncSetAttribute(gemm2<1>, cudaFuncAttributeMaxDynamicSharedMemorySize, SMEM_G);
    cudaFuncSetAttribute(attn_mma, cudaFuncAttributeMaxDynamicSharedMemorySize, ASMEM);

    const int NX4 = MTOT * DMODEL / 4;
    const int NW4 = DMODEL * DMODEL / 4;
    const size_t WS = (size_t)DMODEL * DMODEL;

    conv_f16<<<NX4 / 256, 256>>>(x, x16, NX4);
    {
        dim3 gw(NW4 / 256, 1, 4);
        conv_w<<<gw, 256>>>(Wq, Wk, Wv, Wo, w16, NW4);
    }
    rope_tab<<<(SEQ * 32) / 256, 256>>>(pos, rtab);

    dim3 gq(DMODEL / BN, MTOT / BM, 3);      // (8, 32, 3) = 768 CTAs
    gemm2<1><<<gq, 256, SMEM_G>>>(x16, w16, nullptr, qh, ql, kh, kl, vh, rtab);

    dim3 ga(SEQ / 128, BATCH * NHEADS);      // (16, 32) = 512 CTAs
    attn_mma<<<ga, 256, ASMEM>>>(qh, ql, kh, kl, vh, a16);

    dim3 go(DMODEL / BN, MTOT / BM, 1);      // (8, 32)
    gemm2<0><<<go, 256, SMEM_G>>>(a16, w16 + 3 * WS, out,
                                  nullptr, nullptr, nullptr, nullptr, nullptr, rtab);
}